// round 5
// baseline (speedup 1.0000x reference)
#include <cuda_runtime.h>
#include <math.h>

// Problem constants (fixed by the dataset reference)
constexpr int B   = 4;
constexpr int N   = 10;
constexpr int K   = 5;
constexpr int Q   = 512;
constexpr int D   = 1536;         // 2 * HID
constexpr int T1  = D / 4;        // 384 float4 lanes per row
constexpr int QC  = 32;           // query chunks per batch
constexpr int QPC = Q / QC;       // 16 rows per chunk
constexpr int LPS = T1 / QC;      // 12 lanes per K2 segment

// Scratch (allocation-free: __device__ globals)
__device__ float4 g_psum[QC * B * T1];   // per-chunk column sums
__device__ float  g_psumsq[QC * B * T1]; // per-chunk per-lane sumsq
__device__ float4 g_xbar[B * T1];        // final column mean (already / Q)
__device__ float  g_cpart[B * T1];       // per-lane total sumsq (pre / Q)

// ---------------------------------------------------------------------------
// K1: query partial reduction.  grid=(B,QC), 384 threads, 16 rows/thread.
// ---------------------------------------------------------------------------
__global__ __launch_bounds__(T1) void qreduce_kernel(const float* __restrict__ query)
{
    const int t  = threadIdx.x;
    const int b  = blockIdx.x;
    const int qc = blockIdx.y;

    const float4* qp = reinterpret_cast<const float4*>(query)
                     + (size_t)b * Q * T1 + (size_t)qc * QPC * T1 + t;

    float4 s  = make_float4(0.f, 0.f, 0.f, 0.f);
    float  s2 = 0.f;
    #pragma unroll
    for (int i = 0; i < QPC; ++i) {
        float4 v = qp[(size_t)i * T1];
        s.x += v.x; s.y += v.y; s.z += v.z; s.w += v.w;
        s2  += v.x * v.x + v.y * v.y + v.z * v.z + v.w * v.w;
    }
    const int idx = (qc * B + b) * T1 + t;
    g_psum[idx]   = s;
    g_psumsq[idx] = s2;
}

// ---------------------------------------------------------------------------
// K2: collapse the QC=32 partial chunks into x_bar + per-lane sumsq totals.
// grid=(B, QC) = 128 blocks, 384 threads.
// Block (b,seg) handles lanes [seg*12, seg*12+12).  One WARP per lane:
// thread layout: warp w (=t/32) <-> lane seg*12+w, lane id (=t%32) <-> qc.
// Each thread loads exactly one float4 + one float, then warp shfl-reduce.
// ---------------------------------------------------------------------------
__global__ __launch_bounds__(T1) void collapse_kernel()
{
    const int t   = threadIdx.x;
    const int b   = blockIdx.x;
    const int seg = blockIdx.y;
    const int w   = t >> 5;        // 0..11  -> lane offset within segment
    const int qc  = t & 31;        // 0..31  -> chunk

    const int lane = seg * LPS + w;
    const int idx  = (qc * B + b) * T1 + lane;

    float4 v  = g_psum[idx];
    float  s2 = g_psumsq[idx];

    #pragma unroll
    for (int off = 16; off > 0; off >>= 1) {
        v.x += __shfl_xor_sync(0xFFFFFFFFu, v.x, off);
        v.y += __shfl_xor_sync(0xFFFFFFFFu, v.y, off);
        v.z += __shfl_xor_sync(0xFFFFFFFFu, v.z, off);
        v.w += __shfl_xor_sync(0xFFFFFFFFu, v.w, off);
        s2  += __shfl_xor_sync(0xFFFFFFFFu, s2, off);
    }
    if (qc == 0) {
        constexpr float invQ = 1.0f / (float)Q;
        g_xbar[b * T1 + lane]  = make_float4(v.x * invQ, v.y * invQ,
                                             v.z * invQ, v.w * invQ);
        g_cpart[b * T1 + lane] = s2;
    }
}

// ---------------------------------------------------------------------------
// K3: per-(b,n) prototype block.  grid=40, 384 threads.
// All global loads issued up front (5x support + xbar + cpart -> MLP 7).
// ---------------------------------------------------------------------------
__global__ __launch_bounds__(T1) void proto_kernel(const float* __restrict__ support,
                                                   float* __restrict__ out)
{
    const int t = threadIdx.x;
    const int b = blockIdx.x / N;
    const int n = blockIdx.x % N;

    constexpr float invQ = 1.0f / (float)Q;
    constexpr int   NV   = 2 * K + 2;   // 5 dots, 5 norms, cpart, pad

    const float4* sp = reinterpret_cast<const float4*>(support)
                     + ((size_t)(b * N + n) * K) * T1 + t;

    // Issue everything before consuming (maximize MLP).
    float4 s4[K];
    #pragma unroll
    for (int k = 0; k < K; ++k) s4[k] = sp[(size_t)k * T1];
    const float4 xb = g_xbar[b * T1 + t];
    const float  cp = g_cpart[b * T1 + t];

    float vals[NV];
    #pragma unroll
    for (int k = 0; k < K; ++k) {
        float4 v = s4[k];
        vals[k]     = v.x * xb.x + v.y * xb.y + v.z * xb.z + v.w * xb.w;
        vals[K + k] = v.x * v.x + v.y * v.y + v.z * v.z + v.w * v.w;
    }
    vals[2 * K]     = cp;
    vals[2 * K + 1] = 0.f;

    constexpr int NW = T1 / 32;
    __shared__ float red[NW][NV];
    __shared__ float wsh[K];
    const int wid = t >> 5, lid = t & 31;
    #pragma unroll
    for (int j = 0; j < NV; ++j) {
        float v = vals[j];
        #pragma unroll
        for (int off = 16; off > 0; off >>= 1)
            v += __shfl_xor_sync(0xFFFFFFFFu, v, off);
        if (lid == 0) red[wid][j] = v;
    }
    __syncthreads();

    if (t == 0) {
        float tot[NV];
        #pragma unroll
        for (int j = 0; j < 2 * K + 1; ++j) {
            float a = 0.f;
            #pragma unroll
            for (int w2 = 0; w2 < NW; ++w2) a += red[w2][j];
            tot[j] = a;
        }
        const float c = tot[2 * K] * invQ;     // mean_q ||x_q||^2
        float tk[K], mx = -1e30f;
        #pragma unroll
        for (int k = 0; k < K; ++k) {
            // mean_q -||s - x_q||^2 = -(||s||^2 - 2 s.xbar + c)
            const float m = -(tot[K + k] - 2.0f * tot[k] + c);
            tk[k] = tanhf(m);
            mx = fmaxf(mx, tk[k]);
        }
        float sum = 0.f, e[K];
        #pragma unroll
        for (int k = 0; k < K; ++k) { e[k] = expf(tk[k] - mx); sum += e[k]; }
        const float inv = 1.0f / sum;
        #pragma unroll
        for (int k = 0; k < K; ++k) {
            const float w = e[k] * inv;
            wsh[k] = w;
            out[(size_t)B * N * D + (size_t)(b * N + n) * K + k] = w;  // qgw
        }
    }
    __syncthreads();

    float4 a = make_float4(0.f, 0.f, 0.f, 0.f);
    #pragma unroll
    for (int k = 0; k < K; ++k) {
        const float w = wsh[k];
        a.x += s4[k].x * w; a.y += s4[k].y * w;
        a.z += s4[k].z * w; a.w += s4[k].w * w;
    }
    reinterpret_cast<float4*>(out)[(size_t)(b * N + n) * T1 + t] = a;
}

extern "C" void kernel_launch(void* const* d_in, const int* in_sizes, int n_in,
                              void* d_out, int out_size)
{
    const float* support = (const float*)d_in[0];  // (B, N, K, D)
    const float* query   = (const float*)d_in[1];  // (B, Q, D)
    float* out = (float*)d_out;                    // agg (B,N,D) then qgw (B,N,K,1)

    dim3 g1(B, QC);
    qreduce_kernel<<<g1, T1>>>(query);
    collapse_kernel<<<g1, T1>>>();
    proto_kernel<<<B * N, T1>>>(support, out);
}